// round 5
// baseline (speedup 1.0000x reference)
#include <cuda_runtime.h>
#include <cstdint>

#define D    128
#define SK   36            // xs padded k-stride (floats): conflict-free
#define WB   20            // packed-W per-col stride in uint4 (20*4 mod 32 = 16 banks)
#define MAXN 100000
#define MAXE 1600000
#define SCAN_B 1024

// ---------------- scratch (__device__ globals, allocation-free) -------------
__device__ float    g_h[(size_t)MAXN * D];
__device__ float    g_dinv[MAXN];
__device__ int      g_cnt[MAXN];
__device__ int      g_off[MAXN + 1];
__device__ int      g_cur[MAXN];
__device__ int2     g_csr[MAXE];          // {src, __float_as_int(dinv[src])}
__device__ int      g_bsum[SCAN_B];
__device__ int      g_bpre[SCAN_B];
// packed W fragments: uint4 index (c*16 + kk)*4 + tig  ->
//   {hi(c, kk*8+tig), hi(c, kk*8+tig+4), lo(c, kk*8+tig), lo(c, kk*8+tig+4)}
__device__ uint4    g_Wp[D * 16 * 4];     // 8192 uint4 = 128KB

// ---------------------------------------------------------------------------
__device__ __forceinline__ void tf32_split(float f, uint32_t& hi, uint32_t& lo) {
    uint32_t h;
    asm("cvt.rna.tf32.f32 %0, %1;" : "=r"(h) : "f"(f));
    float fl = f - __uint_as_float(h);
    uint32_t l;
    asm("cvt.rna.tf32.f32 %0, %1;" : "=r"(l) : "f"(fl));
    hi = h; lo = l;
}

__device__ __forceinline__ void mma_tf32(float* c, const uint32_t* a, uint32_t b0, uint32_t b1) {
    asm volatile(
        "mma.sync.aligned.m16n8k8.row.col.f32.tf32.tf32.f32 "
        "{%0,%1,%2,%3}, {%4,%5,%6,%7}, {%8,%9}, {%0,%1,%2,%3};"
        : "+f"(c[0]), "+f"(c[1]), "+f"(c[2]), "+f"(c[3])
        : "r"(a[0]), "r"(a[1]), "r"(a[2]), "r"(a[3]), "r"(b0), "r"(b1));
}

// ---------------------------------------------------------------------------
// 1) zero histogram + pack W fragments (fused)
// ---------------------------------------------------------------------------
__global__ void k_pre(const float* __restrict__ W, int n) {
    int i = blockIdx.x * blockDim.x + threadIdx.x;
    if (i < n) g_cnt[i] = 0;
    if (i < D * 16 * 4) {
        int c   = i >> 6;
        int kk  = (i >> 2) & 15;
        int tig = i & 3;
        int k   = kk * 8 + tig;
        uint32_t h0, l0, h1, l1;
        tf32_split(W[c * D + k],     h0, l0);
        tf32_split(W[c * D + k + 4], h1, l1);
        g_Wp[i] = make_uint4(h0, h1, l0, l1);
    }
}

// 2) histogram of dst (vectorized: 4 edges/thread)
__global__ void k_hist(const int* __restrict__ dst, int e4, int e) {
    int i = blockIdx.x * blockDim.x + threadIdx.x;
    if (i < e4) {
        int4 d = __ldg((const int4*)dst + i);
        atomicAdd(&g_cnt[d.x], 1);
        atomicAdd(&g_cnt[d.y], 1);
        atomicAdd(&g_cnt[d.z], 1);
        atomicAdd(&g_cnt[d.w], 1);
    }
    // tail
    int t = e4 * 4 + i;
    if (i < (e & 3) && t < e) atomicAdd(&g_cnt[dst[t]], 1);
}

// ---------------------------------------------------------------------------
// 3) multi-block scan
// ---------------------------------------------------------------------------
__device__ __forceinline__ int block_incl_scan(int v, int* wsum) {
    int lane = threadIdx.x & 31, wid = threadIdx.x >> 5;
    int nw = blockDim.x >> 5;
    int s = v;
    #pragma unroll
    for (int o = 1; o < 32; o <<= 1) {
        int t = __shfl_up_sync(0xffffffffu, s, o);
        if (lane >= o) s += t;
    }
    if (lane == 31) wsum[wid] = s;
    __syncthreads();
    if (wid == 0) {
        int ws = (lane < nw) ? wsum[lane] : 0;
        #pragma unroll
        for (int o = 1; o < 32; o <<= 1) {
            int t = __shfl_up_sync(0xffffffffu, ws, o);
            if (lane >= o) ws += t;
        }
        if (lane < nw) wsum[lane] = ws;
    }
    __syncthreads();
    return s + (wid > 0 ? wsum[wid - 1] : 0);
}

__global__ void k_scanA(int n) {
    __shared__ int wsum[32];
    int i = blockIdx.x * 1024 + threadIdx.x;
    int v = (i < n) ? g_cnt[i] : 0;
    int incl = block_incl_scan(v, wsum);
    if (i < n) {
        g_off[i]  = incl - v;
        g_dinv[i] = rsqrtf((float)v + 1.0f);   // +1 self loop
    }
    if (threadIdx.x == 1023) g_bsum[blockIdx.x] = incl;
}

__global__ void k_scanB(int nb) {
    __shared__ int wsum[32];
    int t = threadIdx.x;
    int v = (t < nb) ? g_bsum[t] : 0;
    int incl = block_incl_scan(v, wsum);
    if (t < nb) g_bpre[t] = incl - v;
}

__global__ void k_scanC(int n, int e) {
    int i = blockIdx.x * 1024 + threadIdx.x;
    if (i < n) {
        int o = g_off[i] + g_bpre[blockIdx.x];
        g_off[i] = o;
        g_cur[i] = o;
    }
    if (i == 0) g_off[n] = e;
}

// 4) fill CSR (vectorized: 4 edges/thread)
__global__ void k_fill(const int* __restrict__ src, const int* __restrict__ dst,
                       int e4, int e) {
    int i = blockIdx.x * blockDim.x + threadIdx.x;
    if (i < e4) {
        int4 s = __ldg((const int4*)src + i);
        int4 d = __ldg((const int4*)dst + i);
        int p0 = atomicAdd(&g_cur[d.x], 1);
        int p1 = atomicAdd(&g_cur[d.y], 1);
        int p2 = atomicAdd(&g_cur[d.z], 1);
        int p3 = atomicAdd(&g_cur[d.w], 1);
        g_csr[p0] = make_int2(s.x, __float_as_int(__ldg(g_dinv + s.x)));
        g_csr[p1] = make_int2(s.y, __float_as_int(__ldg(g_dinv + s.y)));
        g_csr[p2] = make_int2(s.z, __float_as_int(__ldg(g_dinv + s.z)));
        g_csr[p3] = make_int2(s.w, __float_as_int(__ldg(g_dinv + s.w)));
    }
    int t = e4 * 4 + i;
    if (i < (e & 3) && t < e) {
        int sv = src[t];
        int p = atomicAdd(&g_cur[dst[t]], 1);
        g_csr[p] = make_int2(sv, __float_as_int(__ldg(g_dinv + sv)));
    }
}

// ---------------------------------------------------------------------------
// 5) GEMM: h = x @ W^T, 3xTF32 mma.sync, packed-W fragment smem
//    Block 256 thr, tile 128x128, K chunked by 32.
// ---------------------------------------------------------------------------
__launch_bounds__(256)
__global__ void k_gemm(const float* __restrict__ x, int n) {
    extern __shared__ float smem[];
    float* xs = smem;                              // 128*SK floats (18KB)
    uint4* wb = (uint4*)(smem + 128 * SK);         // 128*WB uint4 (40KB)

    int tid  = threadIdx.x;
    int lane = tid & 31;
    int wid  = tid >> 5;
    int grp  = lane >> 2;
    int tig  = lane & 3;
    int row0 = blockIdx.x * 128;
    int warpRow = wid * 16;

    float acc[16][4];
    #pragma unroll
    for (int nt = 0; nt < 16; nt++)
        #pragma unroll
        for (int i = 0; i < 4; i++) acc[nt][i] = 0.0f;

    for (int kc = 0; kc < 4; kc++) {
        // ---- load x tile ----
        #pragma unroll
        for (int it = 0; it < 4; it++) {
            int i4 = tid + it * 256;   // 1024 float4
            int r = i4 >> 3, q = i4 & 7;
            int row = row0 + r;
            float4 v = make_float4(0.f, 0.f, 0.f, 0.f);
            if (row < n) v = *(const float4*)(x + (size_t)row * D + kc * 32 + q * 4);
            *(float4*)(xs + r * SK + q * 4) = v;
        }
        // ---- load packed W chunk: per col c, 16 uint4 contiguous ----
        #pragma unroll
        for (int it = 0; it < 8; it++) {
            int i = tid + it * 256;    // 2048 uint4
            int c = i >> 4, j = i & 15;
            wb[c * WB + j] = g_Wp[c * 64 + kc * 16 + j];
        }
        __syncthreads();

        #pragma unroll
        for (int ks = 0; ks < 4; ks++) {
            int k0 = ks * 8;
            uint32_t aH[4], aL[4];
            tf32_split(xs[(warpRow + grp)     * SK + k0 + tig],     aH[0], aL[0]);
            tf32_split(xs[(warpRow + grp + 8) * SK + k0 + tig],     aH[1], aL[1]);
            tf32_split(xs[(warpRow + grp)     * SK + k0 + tig + 4], aH[2], aL[2]);
            tf32_split(xs[(warpRow + grp + 8) * SK + k0 + tig + 4], aH[3], aL[3]);
            #pragma unroll
            for (int nt = 0; nt < 16; nt++) {
                uint4 b = wb[(nt * 8 + grp) * WB + ks * 4 + tig];
                mma_tf32(acc[nt], aH, b.x, b.y);   // hi*hi
                mma_tf32(acc[nt], aL, b.x, b.y);   // lo*hi
                mma_tf32(acc[nt], aH, b.z, b.w);   // hi*lo
            }
        }
        __syncthreads();
    }

    #pragma unroll
    for (int nt = 0; nt < 16; nt++) {
        int n0 = nt * 8;
        int r1 = row0 + warpRow + grp;
        int r2 = r1 + 8;
        if (r1 < n) *(float2*)(g_h + (size_t)r1 * D + n0 + 2 * tig) =
            make_float2(acc[nt][0], acc[nt][1]);
        if (r2 < n) *(float2*)(g_h + (size_t)r2 * D + n0 + 2 * tig) =
            make_float2(acc[nt][2], acc[nt][3]);
    }
}

// ---------------------------------------------------------------------------
// 6) gather-aggregate: warp/node, x4 unrolled (MLP=4), fused bias+PReLU
// ---------------------------------------------------------------------------
__launch_bounds__(256)
__global__ void k_agg(const float* __restrict__ b, const float* __restrict__ a,
                      float* __restrict__ out, int n) {
    int node = (blockIdx.x * blockDim.x + threadIdx.x) >> 5;
    int lane = threadIdx.x & 31;
    if (node >= n) return;

    const float4* hb = (const float4*)g_h;
    float dd = g_dinv[node];
    float self = dd * dd;

    float4 hv = hb[(size_t)node * 32 + lane];
    float ax = hv.x * self, ay = hv.y * self, az = hv.z * self, aw = hv.w * self;

    int beg = g_off[node];
    int end = g_off[node + 1];
    int j = beg;

    for (; j + 4 <= end; j += 4) {
        int2 e0 = __ldg(g_csr + j);
        int2 e1 = __ldg(g_csr + j + 1);
        int2 e2 = __ldg(g_csr + j + 2);
        int2 e3 = __ldg(g_csr + j + 3);
        float4 v0 = hb[(size_t)e0.x * 32 + lane];
        float4 v1 = hb[(size_t)e1.x * 32 + lane];
        float4 v2 = hb[(size_t)e2.x * 32 + lane];
        float4 v3 = hb[(size_t)e3.x * 32 + lane];
        float n0 = __int_as_float(e0.y) * dd;
        float n1 = __int_as_float(e1.y) * dd;
        float n2 = __int_as_float(e2.y) * dd;
        float n3 = __int_as_float(e3.y) * dd;
        ax += v0.x * n0 + v1.x * n1 + v2.x * n2 + v3.x * n3;
        ay += v0.y * n0 + v1.y * n1 + v2.y * n2 + v3.y * n3;
        az += v0.z * n0 + v1.z * n1 + v2.z * n2 + v3.z * n3;
        aw += v0.w * n0 + v1.w * n1 + v2.w * n2 + v3.w * n3;
    }
    for (; j < end; j++) {
        int2 e0 = __ldg(g_csr + j);
        float4 v0 = hb[(size_t)e0.x * 32 + lane];
        float n0 = __int_as_float(e0.y) * dd;
        ax += v0.x * n0; ay += v0.y * n0; az += v0.z * n0; aw += v0.w * n0;
    }

    float4 bv = ((const float4*)b)[lane];
    ax += bv.x; ay += bv.y; az += bv.z; aw += bv.w;

    float slope = a[0];
    ax = ax >= 0.f ? ax : slope * ax;
    ay = ay >= 0.f ? ay : slope * ay;
    az = az >= 0.f ? az : slope * az;
    aw = aw >= 0.f ? aw : slope * aw;

    ((float4*)(out + (size_t)node * D))[lane] = make_float4(ax, ay, az, aw);
}

// ---------------------------------------------------------------------------
extern "C" void kernel_launch(void* const* d_in, const int* in_sizes, int n_in,
                              void* d_out, int out_size) {
    const float* x  = (const float*)d_in[0];
    const int*   ei = (const int*)d_in[1];
    const float* W  = (const float*)d_in[2];
    const float* b  = (const float*)d_in[3];
    const float* a  = (const float*)d_in[4];
    float* out = (float*)d_out;

    int n = in_sizes[0] / D;
    int e = in_sizes[1] / 2;
    const int* src = ei;
    const int* dst = ei + e;

    int e4 = e >> 2;
    int nb = (n + 255) / 256;
    int eb4 = (e4 + 255) / 256;
    int sb = (n + 1023) / 1024;

    k_pre<<<nb, 256>>>(W, n);
    k_hist<<<eb4, 256>>>(dst, e4, e);
    k_scanA<<<sb, 1024>>>(n);
    k_scanB<<<1, 128>>>(sb);
    k_scanC<<<sb, 1024>>>(n, e);
    k_fill<<<eb4, 256>>>(src, dst, e4, e);

    const int gemm_smem = 128 * SK * 4 + 128 * WB * 16;   // 18432 + 40960 = 59392
    cudaFuncSetAttribute(k_gemm, cudaFuncAttributeMaxDynamicSharedMemorySize, gemm_smem);
    k_gemm<<<(n + 127) / 128, 256, gemm_smem>>>(x, n);

    k_agg<<<(n * 32 + 255) / 256, 256>>>(b, a, out, n);
}

// round 8
// speedup vs baseline: 1.2147x; 1.2147x over previous
#include <cuda_runtime.h>
#include <cuda_fp16.h>
#include <cstdint>

#define D    128
#define SK   36            // padded smem k-stride: bank=(r*4+k)&31, conflict-free
#define MAXN 100000
#define MAXE 1600000
#define SCAN_B 1024

// ---------------- scratch (__device__ globals, allocation-free) -------------
__device__ __half   g_h[(size_t)MAXN * D];   // x @ W^T, fp16
__device__ float    g_dinv[MAXN];
__device__ int      g_cnt[MAXN];
__device__ int      g_off[MAXN + 1];
__device__ int      g_cur[MAXN];
__device__ int2     g_csr[MAXE];             // {src, __float_as_int(dinv[src])}
__device__ int      g_bsum[SCAN_B];
__device__ int      g_bpre[SCAN_B];
__device__ uint32_t g_Whi[D * D];
__device__ uint32_t g_Wlo[D * D];

// ---------------------------------------------------------------------------
__device__ __forceinline__ void tf32_split(float f, uint32_t& hi, uint32_t& lo) {
    uint32_t h;
    asm("cvt.rna.tf32.f32 %0, %1;" : "=r"(h) : "f"(f));
    float fl = f - __uint_as_float(h);
    uint32_t l;
    asm("cvt.rna.tf32.f32 %0, %1;" : "=r"(l) : "f"(fl));
    hi = h; lo = l;
}

__device__ __forceinline__ void mma_tf32(float* c, const uint32_t* a, const uint32_t* b) {
    asm volatile(
        "mma.sync.aligned.m16n8k8.row.col.f32.tf32.tf32.f32 "
        "{%0,%1,%2,%3}, {%4,%5,%6,%7}, {%8,%9}, {%0,%1,%2,%3};"
        : "+f"(c[0]), "+f"(c[1]), "+f"(c[2]), "+f"(c[3])
        : "r"(a[0]), "r"(a[1]), "r"(a[2]), "r"(a[3]), "r"(b[0]), "r"(b[1]));
}

// ---------------------------------------------------------------------------
// 1) zero histogram + pre-split W into TF32 hi/lo (fused)
// ---------------------------------------------------------------------------
__global__ void k_pre(const float* __restrict__ W, int n) {
    int i = blockIdx.x * blockDim.x + threadIdx.x;
    if (i < n) g_cnt[i] = 0;
    if (i < D * D) {
        uint32_t hi, lo;
        tf32_split(W[i], hi, lo);
        g_Whi[i] = hi; g_Wlo[i] = lo;
    }
}

// 2) histogram of dst
__global__ void k_hist(const int* __restrict__ dst, int e) {
    int i = blockIdx.x * blockDim.x + threadIdx.x;
    if (i < e) atomicAdd(&g_cnt[dst[i]], 1);
}

// ---------------------------------------------------------------------------
// 3) multi-block scan
// ---------------------------------------------------------------------------
__device__ __forceinline__ int block_incl_scan(int v, int* wsum) {
    int lane = threadIdx.x & 31, wid = threadIdx.x >> 5;
    int nw = blockDim.x >> 5;
    int s = v;
    #pragma unroll
    for (int o = 1; o < 32; o <<= 1) {
        int t = __shfl_up_sync(0xffffffffu, s, o);
        if (lane >= o) s += t;
    }
    if (lane == 31) wsum[wid] = s;
    __syncthreads();
    if (wid == 0) {
        int ws = (lane < nw) ? wsum[lane] : 0;
        #pragma unroll
        for (int o = 1; o < 32; o <<= 1) {
            int t = __shfl_up_sync(0xffffffffu, ws, o);
            if (lane >= o) ws += t;
        }
        if (lane < nw) wsum[lane] = ws;
    }
    __syncthreads();
    return s + (wid > 0 ? wsum[wid - 1] : 0);
}

__global__ void k_scanA(int n) {
    __shared__ int wsum[32];
    int i = blockIdx.x * 1024 + threadIdx.x;
    int v = (i < n) ? g_cnt[i] : 0;
    int incl = block_incl_scan(v, wsum);
    if (i < n) {
        g_off[i]  = incl - v;
        g_dinv[i] = rsqrtf((float)v + 1.0f);   // +1 self loop
    }
    if (threadIdx.x == 1023) g_bsum[blockIdx.x] = incl;
}

__global__ void k_scanB(int nb) {
    __shared__ int wsum[32];
    int t = threadIdx.x;
    int v = (t < nb) ? g_bsum[t] : 0;
    int incl = block_incl_scan(v, wsum);
    if (t < nb) g_bpre[t] = incl - v;
}

__global__ void k_scanC(int n, int e) {
    int i = blockIdx.x * 1024 + threadIdx.x;
    if (i < n) {
        int o = g_off[i] + g_bpre[blockIdx.x];
        g_off[i] = o;
        g_cur[i] = o;
    }
    if (i == 0) g_off[n] = e;
}

// 4) fill CSR with packed {src, dinv[src]}
__global__ void k_fill(const int* __restrict__ src, const int* __restrict__ dst, int e) {
    int i = blockIdx.x * blockDim.x + threadIdx.x;
    if (i < e) {
        int s = src[i];
        int p = atomicAdd(&g_cur[dst[i]], 1);
        g_csr[p] = make_int2(s, __float_as_int(__ldg(g_dinv + s)));
    }
}

// ---------------------------------------------------------------------------
// 5) GEMM: h = x @ W^T, 3xTF32 mma.sync; W pre-split in global memory.
//    Block 256 thr, tile 128x128, K chunked by 32. fp16 h stores.
// ---------------------------------------------------------------------------
__launch_bounds__(256)
__global__ void k_gemm(const float* __restrict__ x, int n) {
    extern __shared__ float smem[];
    float*    xs = smem;                                // 128*SK floats
    uint32_t* wh = (uint32_t*)(smem + 128 * SK);        // 128*SK u32
    uint32_t* wl = wh + 128 * SK;

    int tid  = threadIdx.x;
    int lane = tid & 31;
    int wid  = tid >> 5;
    int grp  = lane >> 2;
    int tig  = lane & 3;
    int row0 = blockIdx.x * 128;
    int warpRow = wid * 16;

    float acc[16][4];
    #pragma unroll
    for (int nt = 0; nt < 16; nt++)
        #pragma unroll
        for (int i = 0; i < 4; i++) acc[nt][i] = 0.0f;

    for (int kc = 0; kc < D; kc += 32) {
        #pragma unroll
        for (int it = 0; it < 4; it++) {
            int i4 = tid + it * 256;       // 1024 float4s per array
            int r = i4 >> 3, q = i4 & 7;
            int row = row0 + r;
            float4 v = make_float4(0.f, 0.f, 0.f, 0.f);
            if (row < n) v = *(const float4*)(x + (size_t)row * D + kc + q * 4);
            *(float4*)(xs + r * SK + q * 4) = v;
            *(uint4*)(wh + r * SK + q * 4) = *(const uint4*)(g_Whi + (size_t)r * D + kc + q * 4);
            *(uint4*)(wl + r * SK + q * 4) = *(const uint4*)(g_Wlo + (size_t)r * D + kc + q * 4);
        }
        __syncthreads();

        #pragma unroll
        for (int ks = 0; ks < 4; ks++) {
            int k0 = ks * 8;
            uint32_t aH[4], aL[4];
            tf32_split(xs[(warpRow + grp)     * SK + k0 + tig],     aH[0], aL[0]);
            tf32_split(xs[(warpRow + grp + 8) * SK + k0 + tig],     aH[1], aL[1]);
            tf32_split(xs[(warpRow + grp)     * SK + k0 + tig + 4], aH[2], aL[2]);
            tf32_split(xs[(warpRow + grp + 8) * SK + k0 + tig + 4], aH[3], aL[3]);
            #pragma unroll
            for (int nt = 0; nt < 16; nt++) {
                int n0 = nt * 8;
                uint32_t bH[2], bL[2];
                bH[0] = wh[(n0 + grp) * SK + k0 + tig];
                bH[1] = wh[(n0 + grp) * SK + k0 + tig + 4];
                bL[0] = wl[(n0 + grp) * SK + k0 + tig];
                bL[1] = wl[(n0 + grp) * SK + k0 + tig + 4];
                mma_tf32(acc[nt], aH, bH);
                mma_tf32(acc[nt], aL, bH);
                mma_tf32(acc[nt], aH, bL);
            }
        }
        __syncthreads();
    }

    #pragma unroll
    for (int nt = 0; nt < 16; nt++) {
        int r1 = row0 + warpRow + grp;
        int r2 = r1 + 8;
        __half2 v01 = __float22half2_rn(make_float2(acc[nt][0], acc[nt][1]));
        __half2 v23 = __float22half2_rn(make_float2(acc[nt][2], acc[nt][3]));
        if (r1 < n) ((__half2*)(g_h + (size_t)r1 * D))[nt * 4 + tig] = v01;
        if (r2 < n) ((__half2*)(g_h + (size_t)r2 * D))[nt * 4 + tig] = v23;
    }
}

// ---------------------------------------------------------------------------
// 6) gather-aggregate: warp/node, x4 unrolled (MLP=4), fp16 h gather,
//    fused self-loop + bias + PReLU
// ---------------------------------------------------------------------------
__device__ __forceinline__ void unpack_fma(uint2 u, float nm,
                                           float& ax, float& ay, float& az, float& aw) {
    float2 f0 = __half22float2(*(__half2*)&u.x);
    float2 f1 = __half22float2(*(__half2*)&u.y);
    ax += f0.x * nm; ay += f0.y * nm;
    az += f1.x * nm; aw += f1.y * nm;
}

__launch_bounds__(256)
__global__ void k_agg(const float* __restrict__ b, const float* __restrict__ a,
                      float* __restrict__ out, int n) {
    int node = (blockIdx.x * blockDim.x + threadIdx.x) >> 5;
    int lane = threadIdx.x & 31;
    if (node >= n) return;

    const uint2* hb = (const uint2*)g_h;    // 32 uint2 per row (4 halves each)
    float dd = g_dinv[node];
    float self = dd * dd;

    float ax = 0.f, ay = 0.f, az = 0.f, aw = 0.f;
    unpack_fma(__ldg(hb + (size_t)node * 32 + lane), self, ax, ay, az, aw);

    int beg = g_off[node];
    int end = g_off[node + 1];
    int j = beg;

    for (; j + 4 <= end; j += 4) {
        int2 e0 = __ldg(g_csr + j);
        int2 e1 = __ldg(g_csr + j + 1);
        int2 e2 = __ldg(g_csr + j + 2);
        int2 e3 = __ldg(g_csr + j + 3);
        uint2 v0 = __ldg(hb + (size_t)e0.x * 32 + lane);
        uint2 v1 = __ldg(hb + (size_t)e1.x * 32 + lane);
        uint2 v2 = __ldg(hb + (size_t)e2.x * 32 + lane);
        uint2 v3 = __ldg(hb + (size_t)e3.x * 32 + lane);
        unpack_fma(v0, __int_as_float(e0.y) * dd, ax, ay, az, aw);
        unpack_fma(v1, __int_as_float(e1.y) * dd, ax, ay, az, aw);
        unpack_fma(v2, __int_as_float(e2.y) * dd, ax, ay, az, aw);
        unpack_fma(v3, __int_as_float(e3.y) * dd, ax, ay, az, aw);
    }
    for (; j < end; j++) {
        int2 e0 = __ldg(g_csr + j);
        uint2 v0 = __ldg(hb + (size_t)e0.x * 32 + lane);
        unpack_fma(v0, __int_as_float(e0.y) * dd, ax, ay, az, aw);
    }

    float4 bv = ((const float4*)b)[lane];
    ax += bv.x; ay += bv.y; az += bv.z; aw += bv.w;

    float slope = a[0];
    ax = ax >= 0.f ? ax : slope * ax;
    ay = ay >= 0.f ? ay : slope * ay;
    az = az >= 0.f ? az : slope * az;
    aw = aw >= 0.f ? aw : slope * aw;

    ((float4*)(out + (size_t)node * D))[lane] = make_float4(ax, ay, az, aw);
}

// ---------------------------------------------------------------------------
extern "C" void kernel_launch(void* const* d_in, const int* in_sizes, int n_in,
                              void* d_out, int out_size) {
    const float* x  = (const float*)d_in[0];
    const int*   ei = (const int*)d_in[1];
    const float* W  = (const float*)d_in[2];
    const float* b  = (const float*)d_in[3];
    const float* a  = (const float*)d_in[4];
    float* out = (float*)d_out;

    int n = in_sizes[0] / D;
    int e = in_sizes[1] / 2;
    const int* src = ei;
    const int* dst = ei + e;

    int nb = (n + 255) / 256;
    int eb = (e + 255) / 256;
    int sb = (n + 1023) / 1024;

    k_pre<<<nb, 256>>>(W, n);
    k_hist<<<eb, 256>>>(dst, e);
    k_scanA<<<sb, 1024>>>(n);
    k_scanB<<<1, 128>>>(sb);
    k_scanC<<<sb, 1024>>>(n, e);
    k_fill<<<eb, 256>>>(src, dst, e);

    const int gemm_smem = 3 * 128 * SK * 4;   // 55296 B
    cudaFuncSetAttribute(k_gemm, cudaFuncAttributeMaxDynamicSharedMemorySize, gemm_smem);
    k_gemm<<<(n + 127) / 128, 256, gemm_smem>>>(x, n);

    k_agg<<<(n * 32 + 255) / 256, 256>>>(b, a, out, n);
}